// round 10
// baseline (speedup 1.0000x reference)
#include <cuda_runtime.h>
#include <cstdint>
#include <cstddef>

namespace {
constexpr int kM = 64;
constexpr int kK = 4096;
constexpr int kN = 14336;
constexpr int kBN = 16;               // tensor tile width
constexpr int kBK = 128;              // one quant group per chunk
constexpr int kChunks = kK / kBK;     // 32
constexpr int kPad = 144;             // smem row stride (conflict-free ldmatrix / bcast)
constexpr int kAStage = 64 * kPad;    // 9216 B
constexpr int kBStage = kBN * kPad;   // 2304 B
constexpr int kThreads = 256;
// hybrid partition: tensor covers N[0,10240), dp4a covers N[10240,14336)
constexpr int kTilesT = 640;          // 640 x 16 cols
constexpr int kTilesD = 128;          // 128 x 32 cols
constexpr int kBNd = 32;
constexpr int kNdBase = kTilesT * kBN;  // 10240
constexpr int kGrid = kTilesT + kTilesD;  // 768 = 128 groups of (5 tensor + 1 dp4a)
}

// device-global scratch (no allocations allowed)
__device__ __align__(16) int8_t g_x8[kM * kK];   // packed int8 activations
__device__ int g_xsum[kM * kChunks];             // per (m, group) activation sums

// ---------------- PTX helpers ----------------
__device__ __forceinline__ uint32_t smem_u32(const void* p) {
    return (uint32_t)__cvta_generic_to_shared(p);
}
__device__ __forceinline__ void cp_async16(uint32_t dst, const void* src) {
    asm volatile("cp.async.ca.shared.global [%0], [%1], 16;\n" :: "r"(dst), "l"(src));
}
__device__ __forceinline__ void cp_commit() { asm volatile("cp.async.commit_group;\n"); }
__device__ __forceinline__ void cp_wait_all() { asm volatile("cp.async.wait_group 0;\n" ::: "memory"); }
__device__ __forceinline__ uint32_t prmt(uint32_t a, uint32_t b, uint32_t sel) {
    uint32_t d;
    asm("prmt.b32 %0, %1, %2, %3;" : "=r"(d) : "r"(a), "r"(b), "r"(sel));
    return d;
}
__device__ __forceinline__ int dp4a(int a, int b, int c) {
    int d;
    asm("dp4a.s32.s32 %0, %1, %2, %3;" : "=r"(d) : "r"(a), "r"(b), "r"(c));
    return d;
}
__device__ __forceinline__ void ldmatrix_x4(uint32_t r[4], uint32_t addr) {
    asm volatile("ldmatrix.sync.aligned.m8n8.x4.shared.b16 {%0,%1,%2,%3}, [%4];"
                 : "=r"(r[0]), "=r"(r[1]), "=r"(r[2]), "=r"(r[3]) : "r"(addr));
}
__device__ __forceinline__ void mma_s8(int c[4], uint32_t a0, uint32_t a1, uint32_t a2,
                                       uint32_t a3, uint32_t b0, uint32_t b1) {
    asm volatile(
        "mma.sync.aligned.m16n8k32.row.col.s32.s8.s8.s32 "
        "{%0,%1,%2,%3}, {%4,%5,%6,%7}, {%8,%9}, {%0,%1,%2,%3};\n"
        : "+r"(c[0]), "+r"(c[1]), "+r"(c[2]), "+r"(c[3])
        : "r"(a0), "r"(a1), "r"(a2), "r"(a3), "r"(b0), "r"(b1));
}

// ---------------- pack x -> int8, and xsum[m,g] ----------------
__global__ void pack_x_kernel(const int* __restrict__ x) {
    const int m = blockIdx.x;          // 64 blocks, one activation row each
    const int t = threadIdx.x;         // 256 threads; thread t -> k [16t, 16t+16)
    const int4* xr = (const int4*)x + (size_t)m * (kK / 4);
    uint32_t pk[4];
    int s = 0;
#pragma unroll
    for (int j = 0; j < 4; ++j) {
        int4 v = __ldg(xr + t * 4 + j);
        uint32_t p01 = prmt((uint32_t)v.x, (uint32_t)v.y, 0x0040);
        uint32_t p23 = prmt((uint32_t)v.z, (uint32_t)v.w, 0x0040);
        pk[j] = prmt(p01, p23, 0x5410);
        s = dp4a((int)pk[j], 0x01010101, s);   // signed byte-sum of 4 x values
    }
    *(uint4*)(g_x8 + (size_t)m * kK + t * 16) = make_uint4(pk[0], pk[1], pk[2], pk[3]);
    // 8 threads cover one group of 128 k -> reduce within 8-lane segments
    s += __shfl_xor_sync(0xffffffffu, s, 1, 8);
    s += __shfl_xor_sync(0xffffffffu, s, 2, 8);
    s += __shfl_xor_sync(0xffffffffu, s, 4, 8);
    if ((t & 7) == 0) g_xsum[m * kChunks + (t >> 3)] = s;
}

// ---------------- hybrid GEMM: tensor CTAs + dp4a CTAs ----------------
__global__ void __launch_bounds__(kThreads, 4)
w4a8_gemm(const int* __restrict__ qweight,
          const int* __restrict__ s2_scales,
          const int* __restrict__ s2_zeros,
          const float* __restrict__ input_scales,
          const float* __restrict__ s1_scales,
          const float* __restrict__ bias,
          float* __restrict__ out) {
    __shared__ __align__(16) int8_t As[2][kAStage];
    __shared__ __align__(16) int8_t Bs[2][kBStage];

    const int tid = threadIdx.x;
    const int warp = tid >> 5;
    const int lane = tid & 31;
    const int bid = blockIdx.x;
    const int grp6 = bid / 6, rem6 = bid % 6;   // interleave 5 tensor : 1 dp4a

    if (rem6 < 5) {
        // ==================== TENSOR PATH (R6 verbatim) ====================
        const int n0 = (grp6 * 5 + rem6) * kBN;

        const int nl = tid >> 4;           // 0..15 weight row in tile
        const int seg = tid & 15;          // 8-value segment of the 128-wide chunk
        const int n_glob = n0 + nl;
        const int4* qrow = (const int4*)qweight + (size_t)n_glob * (kK / 4);

        int4 qv0[2], qv1[2];
        int s2r[2], zr[2];

        auto ldg_chunk = [&](int c) {
            const int b = c & 1;
            qv0[b] = __ldcs(qrow + c * 32 + seg * 2);
            qv1[b] = __ldcs(qrow + c * 32 + seg * 2 + 1);
            s2r[b] = __ldg(s2_scales + c * kN + n_glob);
            zr[b]  = __ldg(s2_zeros + c * kN + n_glob);
        };
        auto cp_a = [&](int c, int s) {
#pragma unroll
            for (int j = 0; j < 2; ++j) {
                int id = tid + kThreads * j;           // 0..511
                int row = id >> 3, sg = id & 7;
                cp_async16(smem_u32(&As[s][row * kPad + sg * 16]),
                           g_x8 + (size_t)row * kK + c * kBK + sg * 16);
            }
            cp_commit();
        };
        auto dequant_sts = [&](int c, int s) {
            const int b = c & 1;
            const int sc = s2r[b], zc = zr[b];
            int b0 = qv0[b].x * sc + zc, b1 = qv0[b].y * sc + zc;
            int b2 = qv0[b].z * sc + zc, b3 = qv0[b].w * sc + zc;
            uint32_t p01 = prmt((uint32_t)b0, (uint32_t)b1, 0x0040);
            uint32_t p23 = prmt((uint32_t)b2, (uint32_t)b3, 0x0040);
            uint32_t pk0 = prmt(p01, p23, 0x5410);
            int c0 = qv1[b].x * sc + zc, c1 = qv1[b].y * sc + zc;
            int c2 = qv1[b].z * sc + zc, c3 = qv1[b].w * sc + zc;
            uint32_t q01 = prmt((uint32_t)c0, (uint32_t)c1, 0x0040);
            uint32_t q23 = prmt((uint32_t)c2, (uint32_t)c3, 0x0040);
            uint32_t pk1 = prmt(q01, q23, 0x5410);
            *(uint2*)(&Bs[s][nl * kPad + seg * 8]) = make_uint2(pk0, pk1);
        };

        const int mt = warp & 3;       // 16-row m-tile
        const int nt = warp >> 2;      // 8-col n-tile
        const uint32_t a_off = (uint32_t)((mt * 16 + (lane & 7) + ((lane >> 3) & 1) * 8) * kPad
                                          + ((lane >> 4) & 1) * 16);
        const uint32_t b_off = (uint32_t)((nt * 8 + (lane & 7)) * kPad + (lane >> 3) * 16);
        int acc[2][4] = {};

        ldg_chunk(0);
        ldg_chunk(1);
        cp_a(0, 0);
        dequant_sts(0, 0);
        cp_wait_all();
        __syncthreads();

        for (int c = 0; c < kChunks; ++c) {
            const int s = c & 1;
            if (c + 2 < kChunks) ldg_chunk(c + 2);
            if (c + 1 < kChunks) cp_a(c + 1, s ^ 1);

            const uint32_t abase = smem_u32(&As[s][0]) + a_off;
            const uint32_t bbase = smem_u32(&Bs[s][0]) + b_off;
#pragma unroll
            for (int kp = 0; kp < 2; ++kp) {
                uint32_t bf[4];
                ldmatrix_x4(bf, bbase + kp * 64);
#pragma unroll
                for (int k2 = 0; k2 < 2; ++k2) {
                    uint32_t a[4];
                    ldmatrix_x4(a, abase + (kp * 2 + k2) * 32);
                    mma_s8(acc[kp], a[0], a[1], a[2], a[3], bf[k2 * 2], bf[k2 * 2 + 1]);
                }
            }

            if (c + 1 < kChunks) dequant_sts(c + 1, s ^ 1);
            cp_wait_all();
            __syncthreads();
        }

        const int r = mt * 16 + (lane >> 2);
        const int n = n0 + nt * 8 + (lane & 3) * 2;
        const float is0 = input_scales[r];
        const float is1 = input_scales[r + 8];
        const float s1a = s1_scales[n], s1b = s1_scales[n + 1];
        const float ba = bias[n], bb = bias[n + 1];
        const int a0 = acc[0][0] + acc[1][0], a1 = acc[0][1] + acc[1][1];
        const int a2 = acc[0][2] + acc[1][2], a3 = acc[0][3] + acc[1][3];
        *(float2*)(out + (size_t)r * kN + n) =
            make_float2((float)a0 * is0 * s1a + ba, (float)a1 * is0 * s1b + bb);
        *(float2*)(out + (size_t)(r + 8) * kN + n) =
            make_float2((float)a2 * is1 * s1a + ba, (float)a3 * is1 * s1b + bb);
    } else {
        // ==================== DP4A PATH (fma/alu pipes) ====================
        // tile: 32 cols x 64 rows; thread = 1 col x 8 rows (warp m-group)
        const int n0 = kNdBase + grp6 * kBNd;
        const int n = n0 + lane;                 // lane -> column (coalesced)
        const int mrow0 = warp * 8;              // 8 m-rows per warp
        const int4* qr = (const int4*)qweight + (size_t)n * (kK / 4);

        auto cp_a = [&](int c, int s) {
#pragma unroll
            for (int j = 0; j < 2; ++j) {
                int id = tid + kThreads * j;
                int row = id >> 3, sg = id & 7;
                cp_async16(smem_u32(&As[s][row * kPad + sg * 16]),
                           g_x8 + (size_t)row * kK + c * kBK + sg * 16);
            }
            cp_commit();
        };

        int acc[8] = {};
        int P[8] = {};
        int4 qv[4];
        uint32_t qpk[4];

        auto ldq = [&](int kb16) {               // load 16 raw q words (one k16 block)
            if (kb16 < kK / 16) {
#pragma unroll
                for (int i = 0; i < 4; ++i) qv[i] = __ldcs(qr + kb16 * 4 + i);
            }
        };

        ldq(0);
        cp_a(0, 0);
        cp_wait_all();
        __syncthreads();

        for (int c = 0; c < kChunks; ++c) {
            const int s = c & 1;
            if (c + 1 < kChunks) cp_a(c + 1, s ^ 1);

#pragma unroll
            for (int j = 0; j < 8; ++j) {        // 8 k16-blocks per chunk
                // pack current block (q in [0,15] -> exact bytes)
#pragma unroll
                for (int i = 0; i < 4; ++i) {
                    uint32_t p01 = prmt((uint32_t)qv[i].x, (uint32_t)qv[i].y, 0x0040);
                    uint32_t p23 = prmt((uint32_t)qv[i].z, (uint32_t)qv[i].w, 0x0040);
                    qpk[i] = prmt(p01, p23, 0x5410);
                }
                ldq(c * 8 + j + 1);              // prefetch next block
                const int koff = j * 16;
#pragma unroll
                for (int q = 0; q < 4; ++q) {
#pragma unroll
                    for (int mm = 0; mm < 8; ++mm) {
                        uint32_t xw = *(const uint32_t*)
                            &As[s][(mrow0 + mm) * kPad + koff + q * 4];  // broadcast LDS
                        P[mm] = dp4a((int)xw, (int)qpk[q], P[mm]);
                    }
                }
            }
            // group fold: acc += s2*P + z*xsum (exact int32)
            const int s2v = __ldg(s2_scales + (size_t)c * kN + n);
            const int zzv = __ldg(s2_zeros + (size_t)c * kN + n);
#pragma unroll
            for (int mm = 0; mm < 8; ++mm) {
                const int xs = __ldg(&g_xsum[(mrow0 + mm) * kChunks + c]);
                acc[mm] += s2v * P[mm] + zzv * xs;
                P[mm] = 0;
            }
            cp_wait_all();
            __syncthreads();
        }

        // epilogue: lane-coalesced stores
        const float s1v = s1_scales[n];
        const float bv = bias[n];
#pragma unroll
        for (int mm = 0; mm < 8; ++mm) {
            const int m = mrow0 + mm;
            out[(size_t)m * kN + n] = (float)acc[mm] * input_scales[m] * s1v + bv;
        }
    }
}

extern "C" void kernel_launch(void* const* d_in, const int* in_sizes, int n_in,
                              void* d_out, int out_size) {
    const int* x           = (const int*)d_in[0];
    const float* in_scales = (const float*)d_in[1];
    // d_in[2] = input_sum (unused)
    const int* qweight     = (const int*)d_in[3];
    const int* s2_scales   = (const int*)d_in[4];
    const int* s2_zeros    = (const int*)d_in[5];
    const float* s1_scales = (const float*)d_in[6];
    const float* bias      = (const float*)d_in[7];
    float* out             = (float*)d_out;
    (void)in_sizes; (void)n_in; (void)out_size;

    pack_x_kernel<<<kM, kThreads>>>(x);
    w4a8_gemm<<<kGrid, kThreads>>>(qweight, s2_scales, s2_zeros,
                                   in_scales, s1_scales, bias, out);
}

// round 11
// speedup vs baseline: 2.8386x; 2.8386x over previous
#include <cuda_runtime.h>
#include <cstdint>
#include <cstddef>

namespace {
constexpr int kM = 64;
constexpr int kK = 4096;
constexpr int kN = 14336;
constexpr int kBN = 16;               // tensor tile width
constexpr int kBK = 128;              // one quant group per chunk
constexpr int kChunks = kK / kBK;     // 32
constexpr int kPad = 144;             // A smem row stride (conflict-free ldmatrix)
constexpr int kAStage = 64 * kPad;    // 9216 B
constexpr int kBStage = kBN * kPad;   // 2304 B
constexpr int kThreads = 256;
// hybrid partition: tensor covers N[0,10240), dp4a covers N[10240,14336)
constexpr int kTilesT = 640;              // 640 x 16 cols (tensor)
constexpr int kTilesD = 128;              // 128 x 32 cols (dp4a)
constexpr int kBNd = 32;
constexpr int kNdBase = kTilesT * kBN;    // 10240
constexpr int kGrid = kTilesT + kTilesD;  // 768 = 128 groups of (5 tensor + 1 dp4a)
// dp4a q staging: 32 rows x 512B (+16 pad) per stage
constexpr int kQPad = 528;
constexpr int kQStage = kBNd * kQPad;     // 16896 B
// dynamic smem layout
constexpr int kOffA = 0;                       // 2 x kAStage
constexpr int kOffB = 2 * kAStage;             // 2 x kBStage
constexpr int kOffQ = kOffB + 2 * kBStage;     // 2 x kQStage
constexpr int kSmemBytes = kOffQ + 2 * kQStage;  // 56832
}

// device-global scratch (no allocations allowed)
__device__ __align__(16) int8_t g_x8[kM * kK];   // packed int8 activations
__device__ int g_xsum[kM * kChunks];             // per (m, group) activation sums

// ---------------- PTX helpers ----------------
__device__ __forceinline__ uint32_t smem_u32(const void* p) {
    return (uint32_t)__cvta_generic_to_shared(p);
}
__device__ __forceinline__ void cp_async16(uint32_t dst, const void* src) {
    asm volatile("cp.async.ca.shared.global [%0], [%1], 16;\n" :: "r"(dst), "l"(src));
}
__device__ __forceinline__ void cp_commit() { asm volatile("cp.async.commit_group;\n"); }
__device__ __forceinline__ void cp_wait_all() { asm volatile("cp.async.wait_group 0;\n" ::: "memory"); }
__device__ __forceinline__ uint32_t prmt(uint32_t a, uint32_t b, uint32_t sel) {
    uint32_t d;
    asm("prmt.b32 %0, %1, %2, %3;" : "=r"(d) : "r"(a), "r"(b), "r"(sel));
    return d;
}
__device__ __forceinline__ int dp4a(int a, int b, int c) {
    int d;
    asm("dp4a.s32.s32 %0, %1, %2, %3;" : "=r"(d) : "r"(a), "r"(b), "r"(c));
    return d;
}
__device__ __forceinline__ void ldmatrix_x4(uint32_t r[4], uint32_t addr) {
    asm volatile("ldmatrix.sync.aligned.m8n8.x4.shared.b16 {%0,%1,%2,%3}, [%4];"
                 : "=r"(r[0]), "=r"(r[1]), "=r"(r[2]), "=r"(r[3]) : "r"(addr));
}
__device__ __forceinline__ void mma_s8(int c[4], uint32_t a0, uint32_t a1, uint32_t a2,
                                       uint32_t a3, uint32_t b0, uint32_t b1) {
    asm volatile(
        "mma.sync.aligned.m16n8k32.row.col.s32.s8.s8.s32 "
        "{%0,%1,%2,%3}, {%4,%5,%6,%7}, {%8,%9}, {%0,%1,%2,%3};\n"
        : "+r"(c[0]), "+r"(c[1]), "+r"(c[2]), "+r"(c[3])
        : "r"(a0), "r"(a1), "r"(a2), "r"(a3), "r"(b0), "r"(b1));
}

// ---------------- pack x -> int8, and xsum[m,g] ----------------
__global__ void pack_x_kernel(const int* __restrict__ x) {
    const int m = blockIdx.x;          // 64 blocks, one activation row each
    const int t = threadIdx.x;         // 256 threads; thread t -> k [16t, 16t+16)
    const int4* xr = (const int4*)x + (size_t)m * (kK / 4);
    uint32_t pk[4];
    int s = 0;
#pragma unroll
    for (int j = 0; j < 4; ++j) {
        int4 v = __ldg(xr + t * 4 + j);
        uint32_t p01 = prmt((uint32_t)v.x, (uint32_t)v.y, 0x0040);
        uint32_t p23 = prmt((uint32_t)v.z, (uint32_t)v.w, 0x0040);
        pk[j] = prmt(p01, p23, 0x5410);
        s = dp4a((int)pk[j], 0x01010101, s);   // signed byte-sum of 4 x values
    }
    *(uint4*)(g_x8 + (size_t)m * kK + t * 16) = make_uint4(pk[0], pk[1], pk[2], pk[3]);
    s += __shfl_xor_sync(0xffffffffu, s, 1, 8);
    s += __shfl_xor_sync(0xffffffffu, s, 2, 8);
    s += __shfl_xor_sync(0xffffffffu, s, 4, 8);
    if ((t & 7) == 0) g_xsum[m * kChunks + (t >> 3)] = s;
}

// ---------------- hybrid GEMM: tensor CTAs + smem-staged dp4a CTAs ----------------
__global__ void __launch_bounds__(kThreads, 4)
w4a8_gemm(const int* __restrict__ qweight,
          const int* __restrict__ s2_scales,
          const int* __restrict__ s2_zeros,
          const float* __restrict__ input_scales,
          const float* __restrict__ s1_scales,
          const float* __restrict__ bias,
          float* __restrict__ out) {
    extern __shared__ __align__(16) int8_t sm[];
    int8_t* As = sm + kOffA;                  // 2 stages of kAStage
    int8_t* Bsm = sm + kOffB;                 // 2 stages of kBStage
    int8_t* Qs = sm + kOffQ;                  // 2 stages of kQStage

    const int tid = threadIdx.x;
    const int warp = tid >> 5;
    const int lane = tid & 31;
    const int bid = blockIdx.x;
    const int grp6 = bid / 6, rem6 = bid % 6;   // interleave 5 tensor : 1 dp4a

    // shared A-tile loader (both paths)
    auto cp_a = [&](int c, int s) {
#pragma unroll
        for (int j = 0; j < 2; ++j) {
            int id = tid + kThreads * j;           // 0..511
            int row = id >> 3, sg = id & 7;
            cp_async16(smem_u32(As + s * kAStage + row * kPad + sg * 16),
                       g_x8 + (size_t)row * kK + c * kBK + sg * 16);
        }
    };

    if (rem6 < 5) {
        // ==================== TENSOR PATH (R6 verbatim) ====================
        const int n0 = (grp6 * 5 + rem6) * kBN;

        const int nl = tid >> 4;           // 0..15 weight row in tile
        const int seg = tid & 15;          // 8-value segment of the 128-wide chunk
        const int n_glob = n0 + nl;
        const int4* qrow = (const int4*)qweight + (size_t)n_glob * (kK / 4);

        int4 qv0[2], qv1[2];
        int s2r[2], zr[2];

        auto ldg_chunk = [&](int c) {
            const int b = c & 1;
            qv0[b] = __ldcs(qrow + c * 32 + seg * 2);
            qv1[b] = __ldcs(qrow + c * 32 + seg * 2 + 1);
            s2r[b] = __ldg(s2_scales + c * kN + n_glob);
            zr[b]  = __ldg(s2_zeros + c * kN + n_glob);
        };
        auto dequant_sts = [&](int c, int s) {
            const int b = c & 1;
            const int sc = s2r[b], zc = zr[b];
            int b0 = qv0[b].x * sc + zc, b1 = qv0[b].y * sc + zc;
            int b2 = qv0[b].z * sc + zc, b3 = qv0[b].w * sc + zc;
            uint32_t p01 = prmt((uint32_t)b0, (uint32_t)b1, 0x0040);
            uint32_t p23 = prmt((uint32_t)b2, (uint32_t)b3, 0x0040);
            uint32_t pk0 = prmt(p01, p23, 0x5410);
            int c0 = qv1[b].x * sc + zc, c1 = qv1[b].y * sc + zc;
            int c2 = qv1[b].z * sc + zc, c3 = qv1[b].w * sc + zc;
            uint32_t q01 = prmt((uint32_t)c0, (uint32_t)c1, 0x0040);
            uint32_t q23 = prmt((uint32_t)c2, (uint32_t)c3, 0x0040);
            uint32_t pk1 = prmt(q01, q23, 0x5410);
            *(uint2*)(Bsm + s * kBStage + nl * kPad + seg * 8) = make_uint2(pk0, pk1);
        };

        const int mt = warp & 3;       // 16-row m-tile
        const int nt = warp >> 2;      // 8-col n-tile
        const uint32_t a_off = (uint32_t)((mt * 16 + (lane & 7) + ((lane >> 3) & 1) * 8) * kPad
                                          + ((lane >> 4) & 1) * 16);
        const uint32_t b_off = (uint32_t)((nt * 8 + (lane & 7)) * kPad + (lane >> 3) * 16);
        int acc[2][4] = {};

        ldg_chunk(0);
        ldg_chunk(1);
        cp_a(0, 0);
        cp_commit();
        dequant_sts(0, 0);
        cp_wait_all();
        __syncthreads();

        for (int c = 0; c < kChunks; ++c) {
            const int s = c & 1;
            if (c + 2 < kChunks) ldg_chunk(c + 2);
            if (c + 1 < kChunks) { cp_a(c + 1, s ^ 1); cp_commit(); }

            const uint32_t abase = smem_u32(As + s * kAStage) + a_off;
            const uint32_t bbase = smem_u32(Bsm + s * kBStage) + b_off;
#pragma unroll
            for (int kp = 0; kp < 2; ++kp) {
                uint32_t bf[4];
                ldmatrix_x4(bf, bbase + kp * 64);
#pragma unroll
                for (int k2 = 0; k2 < 2; ++k2) {
                    uint32_t a[4];
                    ldmatrix_x4(a, abase + (kp * 2 + k2) * 32);
                    mma_s8(acc[kp], a[0], a[1], a[2], a[3], bf[k2 * 2], bf[k2 * 2 + 1]);
                }
            }

            if (c + 1 < kChunks) dequant_sts(c + 1, s ^ 1);
            cp_wait_all();
            __syncthreads();
        }

        const int r = mt * 16 + (lane >> 2);
        const int n = n0 + nt * 8 + (lane & 3) * 2;
        const float is0 = input_scales[r];
        const float is1 = input_scales[r + 8];
        const float s1a = s1_scales[n], s1b = s1_scales[n + 1];
        const float ba = bias[n], bb = bias[n + 1];
        const int a0 = acc[0][0] + acc[1][0], a1 = acc[0][1] + acc[1][1];
        const int a2 = acc[0][2] + acc[1][2], a3 = acc[0][3] + acc[1][3];
        *(float2*)(out + (size_t)r * kN + n) =
            make_float2((float)a0 * is0 * s1a + ba, (float)a1 * is0 * s1b + bb);
        *(float2*)(out + (size_t)(r + 8) * kN + n) =
            make_float2((float)a2 * is1 * s1a + ba, (float)a3 * is1 * s1b + bb);
    } else {
        // ============ DP4A PATH: smem-staged coalesced weights ============
        const int n0 = kNdBase + grp6 * kBNd;
        const int n = n0 + lane;                 // lane -> column
        const int mrow0 = warp * 8;              // 8 m-rows per warp

        // coalesced q stage: 32 rows x 512B; 4 x 16B per thread
        auto cp_q = [&](int c, int s) {
#pragma unroll
            for (int j = 0; j < 4; ++j) {
                int id = tid + kThreads * j;       // 0..1023
                int row = id >> 5, sg = id & 31;   // row 0..31, 16B seg 0..31
                cp_async16(smem_u32(Qs + s * kQStage + row * kQPad + sg * 16),
                           (const char*)qweight
                               + ((size_t)(n0 + row) * kK + c * kBK + sg * 4) * 4);
            }
        };

        int acc[8] = {};

        cp_q(0, 0);
        cp_a(0, 0);
        cp_commit();
        cp_wait_all();
        __syncthreads();

        for (int c = 0; c < kChunks; ++c) {
            const int s = c & 1;
            if (c + 1 < kChunks) { cp_q(c + 1, s ^ 1); cp_a(c + 1, s ^ 1); cp_commit(); }

            // per-chunk scalars (latency covered by the block loop below)
            const int s2v = __ldg(s2_scales + (size_t)c * kN + n);
            const int zzv = __ldg(s2_zeros + (size_t)c * kN + n);

            int P[8] = {};
            const int8_t* qrow_s = Qs + s * kQStage + lane * kQPad;
            const int8_t* arow_s = As + s * kAStage;
#pragma unroll
            for (int kb = 0; kb < 8; ++kb) {       // 8 x 16-k blocks
                // this column's 16 raw q ints (conflict-free LDS.128)
                uint4 qv0 = *(const uint4*)(qrow_s + kb * 64);
                uint4 qv1 = *(const uint4*)(qrow_s + kb * 64 + 16);
                uint4 qv2 = *(const uint4*)(qrow_s + kb * 64 + 32);
                uint4 qv3 = *(const uint4*)(qrow_s + kb * 64 + 48);
                uint32_t qpk[4];
                qpk[0] = prmt(prmt(qv0.x, qv0.y, 0x0040), prmt(qv0.z, qv0.w, 0x0040), 0x5410);
                qpk[1] = prmt(prmt(qv1.x, qv1.y, 0x0040), prmt(qv1.z, qv1.w, 0x0040), 0x5410);
                qpk[2] = prmt(prmt(qv2.x, qv2.y, 0x0040), prmt(qv2.z, qv2.w, 0x0040), 0x5410);
                qpk[3] = prmt(prmt(qv3.x, qv3.y, 0x0040), prmt(qv3.z, qv3.w, 0x0040), 0x5410);
#pragma unroll
                for (int mm = 0; mm < 8; ++mm) {   // broadcast x row, 4 dp4a
                    uint4 xw = *(const uint4*)(arow_s + (mrow0 + mm) * kPad + kb * 16);
                    P[mm] = dp4a((int)xw.x, (int)qpk[0], P[mm]);
                    P[mm] = dp4a((int)xw.y, (int)qpk[1], P[mm]);
                    P[mm] = dp4a((int)xw.z, (int)qpk[2], P[mm]);
                    P[mm] = dp4a((int)xw.w, (int)qpk[3], P[mm]);
                }
            }
            // exact group fold: acc += s2*P + z*xsum
#pragma unroll
            for (int mm = 0; mm < 8; ++mm) {
                const int xs = __ldg(&g_xsum[(mrow0 + mm) * kChunks + c]);
                acc[mm] += s2v * P[mm] + zzv * xs;
            }
            cp_wait_all();
            __syncthreads();
        }

        const float s1v = s1_scales[n];
        const float bv = bias[n];
#pragma unroll
        for (int mm = 0; mm < 8; ++mm) {
            const int m = mrow0 + mm;
            out[(size_t)m * kN + n] = (float)acc[mm] * input_scales[m] * s1v + bv;
        }
    }
}

extern "C" void kernel_launch(void* const* d_in, const int* in_sizes, int n_in,
                              void* d_out, int out_size) {
    const int* x           = (const int*)d_in[0];
    const float* in_scales = (const float*)d_in[1];
    // d_in[2] = input_sum (unused)
    const int* qweight     = (const int*)d_in[3];
    const int* s2_scales   = (const int*)d_in[4];
    const int* s2_zeros    = (const int*)d_in[5];
    const float* s1_scales = (const float*)d_in[6];
    const float* bias      = (const float*)d_in[7];
    float* out             = (float*)d_out;
    (void)in_sizes; (void)n_in; (void)out_size;

    cudaFuncSetAttribute(w4a8_gemm, cudaFuncAttributeMaxDynamicSharedMemorySize,
                         kSmemBytes);

    pack_x_kernel<<<kM, kThreads>>>(x);
    w4a8_gemm<<<kGrid, kThreads, kSmemBytes>>>(qweight, s2_scales, s2_zeros,
                                               in_scales, s1_scales, bias, out);
}

// round 12
// speedup vs baseline: 3.7090x; 1.3066x over previous
#include <cuda_runtime.h>
#include <cstdint>
#include <cstddef>

namespace {
constexpr int kM = 64;
constexpr int kK = 4096;
constexpr int kN = 14336;
constexpr int kBN = 16;               // tile width
constexpr int kBK = 128;              // one quant group per chunk
constexpr int kChunks = kK / kBK;     // 32
constexpr int kTiles = kN / kBN;      // 896 work units
constexpr int kPad = 144;             // smem row stride (conflict-free ldmatrix)
constexpr int kAStage = 64 * kPad;    // 9216 B
constexpr int kBStage = kBN * kPad;   // 2304 B
constexpr int kThreads = 256;
}

// device-global scratch (no allocations allowed)
__device__ __align__(16) int8_t g_x8[kM * kK];  // packed int8 activations
__device__ int g_counter;                       // work-stealing cursor

__global__ void pack_x_kernel(const int* __restrict__ x, int gemm_grid) {
    if (blockIdx.x == 0 && threadIdx.x == 0) g_counter = gemm_grid;
    int idx = blockIdx.x * blockDim.x + threadIdx.x;  // int4 index over M*K/4
    int4 v = __ldg(((const int4*)x) + idx);
    uint32_t w = (uint32_t)(v.x & 0xff) | ((uint32_t)(v.y & 0xff) << 8)
               | ((uint32_t)(v.z & 0xff) << 16) | ((uint32_t)(v.w & 0xff) << 24);
    ((uint32_t*)g_x8)[idx] = w;
}

// ---------------- PTX helpers ----------------
__device__ __forceinline__ uint32_t smem_u32(const void* p) {
    return (uint32_t)__cvta_generic_to_shared(p);
}
__device__ __forceinline__ void cp_async16(uint32_t dst, const void* src) {
    asm volatile("cp.async.ca.shared.global [%0], [%1], 16;\n" :: "r"(dst), "l"(src));
}
__device__ __forceinline__ void cp_commit() { asm volatile("cp.async.commit_group;\n"); }
__device__ __forceinline__ void cp_wait_all() { asm volatile("cp.async.wait_group 0;\n" ::: "memory"); }
__device__ __forceinline__ uint32_t prmt(uint32_t a, uint32_t b, uint32_t sel) {
    uint32_t d;
    asm("prmt.b32 %0, %1, %2, %3;" : "=r"(d) : "r"(a), "r"(b), "r"(sel));
    return d;
}
__device__ __forceinline__ void ldmatrix_x4(uint32_t r[4], uint32_t addr) {
    asm volatile("ldmatrix.sync.aligned.m8n8.x4.shared.b16 {%0,%1,%2,%3}, [%4];"
                 : "=r"(r[0]), "=r"(r[1]), "=r"(r[2]), "=r"(r[3]) : "r"(addr));
}
__device__ __forceinline__ void mma_s8(int c[4], uint32_t a0, uint32_t a1, uint32_t a2,
                                       uint32_t a3, uint32_t b0, uint32_t b1) {
    asm volatile(
        "mma.sync.aligned.m16n8k32.row.col.s32.s8.s8.s32 "
        "{%0,%1,%2,%3}, {%4,%5,%6,%7}, {%8,%9}, {%0,%1,%2,%3};\n"
        : "+r"(c[0]), "+r"(c[1]), "+r"(c[2]), "+r"(c[3])
        : "r"(a0), "r"(a1), "r"(a2), "r"(a3), "r"(b0), "r"(b1));
}

// ------ persistent work-stealing GEMM: R6 inner loop, occ 4, no ragged waves ------
__global__ void __launch_bounds__(kThreads, 4)
w4a8_gemm(const int* __restrict__ qweight,
          const int* __restrict__ s2_scales,
          const int* __restrict__ s2_zeros,
          const float* __restrict__ input_scales,
          const float* __restrict__ s1_scales,
          const float* __restrict__ bias,
          float* __restrict__ out) {
    __shared__ __align__(16) int8_t As[2][kAStage];
    __shared__ __align__(16) int8_t Bs[2][kBStage];
    __shared__ int s_next;

    const int tid = threadIdx.x;
    const int warp = tid >> 5;
    const int lane = tid & 31;

    // ---- producer mapping: 16 rows x 16 segments (8 values each) ----
    const int nl = tid >> 4;           // 0..15 weight row in tile
    const int seg = tid & 15;          // 8-value segment within the 128-wide chunk

    int n_glob;                        // producer's current weight row (tile-dep)
    const int4* qrow;
    auto set_tile = [&](int t) {
        n_glob = t * kBN + nl;
        qrow = (const int4*)qweight + (size_t)n_glob * (kK / 4);
    };

    // depth-2 register prefetch: virtual chunk j lives in slot j&1
    int4 qv0[2], qv1[2];
    int s2r[2], zr[2];

    auto ldg_chunk = [&](int c) {      // c = chunk index within CURRENT producer tile
        const int b = c & 1;
        qv0[b] = __ldcs(qrow + c * 32 + seg * 2);
        qv1[b] = __ldcs(qrow + c * 32 + seg * 2 + 1);
        s2r[b] = __ldg(s2_scales + c * kN + n_glob);
        zr[b]  = __ldg(s2_zeros + c * kN + n_glob);
    };
    auto cp_a = [&](int c, int s) {
#pragma unroll
        for (int j = 0; j < 2; ++j) {
            int id = tid + kThreads * j;           // 0..511
            int row = id >> 3, sg = id & 7;
            cp_async16(smem_u32(&As[s][row * kPad + sg * 16]),
                       g_x8 + (size_t)row * kK + c * kBK + sg * 16);
        }
        cp_commit();
    };
    auto dequant_sts = [&](int c, int s) {         // c only selects the reg slot
        const int b = c & 1;
        const int sc = s2r[b], zc = zr[b];
        int b0 = qv0[b].x * sc + zc, b1 = qv0[b].y * sc + zc;
        int b2 = qv0[b].z * sc + zc, b3 = qv0[b].w * sc + zc;
        uint32_t p01 = prmt((uint32_t)b0, (uint32_t)b1, 0x0040);
        uint32_t p23 = prmt((uint32_t)b2, (uint32_t)b3, 0x0040);
        uint32_t pk0 = prmt(p01, p23, 0x5410);
        int c0 = qv1[b].x * sc + zc, c1 = qv1[b].y * sc + zc;
        int c2 = qv1[b].z * sc + zc, c3 = qv1[b].w * sc + zc;
        uint32_t q01 = prmt((uint32_t)c0, (uint32_t)c1, 0x0040);
        uint32_t q23 = prmt((uint32_t)c2, (uint32_t)c3, 0x0040);
        uint32_t pk1 = prmt(q01, q23, 0x5410);
        *(uint2*)(&Bs[s][nl * kPad + seg * 8]) = make_uint2(pk0, pk1);
    };

    // ---- consumer mapping (validated): warp -> (m-tile, n-tile) ----
    const int mt = warp & 3;       // 16-row m-tile
    const int nt = warp >> 2;      // 8-col n-tile
    const uint32_t a_off = (uint32_t)((mt * 16 + (lane & 7) + ((lane >> 3) & 1) * 8) * kPad
                                      + ((lane >> 4) & 1) * 16);
    const uint32_t b_off = (uint32_t)((nt * 8 + (lane & 7)) * kPad + (lane >> 3) * 16);

    // ---- prologue: first tile's pipeline primed (exactly as R6) ----
    int tile = blockIdx.x;
    int nxt = kTiles;
    set_tile(tile);
    ldg_chunk(0);
    ldg_chunk(1);
    cp_a(0, 0);
    dequant_sts(0, 0);
    cp_wait_all();
    __syncthreads();

    while (tile < kTiles) {
        const int n0_out = tile * kBN;
        int acc[2][4] = {};

        for (int c = 0; c < kChunks; ++c) {
            const int s = c & 1;
            if (c == 27 && tid == 0) s_next = atomicAdd(&g_counter, 1);

            // q prefetch for virtual chunk c+2 (rolls onto next tile's 0/1)
            if (c + 2 < kChunks) {
                ldg_chunk(c + 2);
            } else {
                if (c + 2 == kChunks) {           // c == 30: switch producer tile
                    nxt = s_next;                 // visible: synced at end of 27,28,29
                    if (nxt < kTiles) set_tile(nxt);
                }
                if (nxt < kTiles) ldg_chunk(c + 2 - kChunks);
            }
            // A stage for virtual chunk c+1
            if (c + 1 < kChunks) cp_a(c + 1, s ^ 1);
            else if (nxt < kTiles) cp_a(0, s ^ 1);

            const uint32_t abase = smem_u32(&As[s][0]) + a_off;
            const uint32_t bbase = smem_u32(&Bs[s][0]) + b_off;
#pragma unroll
            for (int kp = 0; kp < 2; ++kp) {
                uint32_t bf[4];
                ldmatrix_x4(bf, bbase + kp * 64);
#pragma unroll
                for (int k2 = 0; k2 < 2; ++k2) {
                    uint32_t a[4];
                    ldmatrix_x4(a, abase + (kp * 2 + k2) * 32);
                    mma_s8(acc[kp], a[0], a[1], a[2], a[3], bf[k2 * 2], bf[k2 * 2 + 1]);
                }
            }

            // B stage for virtual chunk c+1
            if (c + 1 < kChunks) dequant_sts(c + 1, s ^ 1);
            else if (nxt < kTiles) dequant_sts(0, s ^ 1);
            cp_wait_all();
            __syncthreads();
        }

        // ---- fused epilogue for this tile ----
        {
            const int r = mt * 16 + (lane >> 2);
            const int n = n0_out + nt * 8 + (lane & 3) * 2;
            const float is0 = input_scales[r];
            const float is1 = input_scales[r + 8];
            const float s1a = s1_scales[n], s1b = s1_scales[n + 1];
            const float ba = bias[n], bb = bias[n + 1];
            const int a0 = acc[0][0] + acc[1][0], a1 = acc[0][1] + acc[1][1];
            const int a2 = acc[0][2] + acc[1][2], a3 = acc[0][3] + acc[1][3];
            *(float2*)(out + (size_t)r * kN + n) =
                make_float2((float)a0 * is0 * s1a + ba, (float)a1 * is0 * s1b + bb);
            *(float2*)(out + (size_t)(r + 8) * kN + n) =
                make_float2((float)a2 * is1 * s1a + ba, (float)a3 * is1 * s1b + bb);
        }
        tile = nxt;
    }
}

extern "C" void kernel_launch(void* const* d_in, const int* in_sizes, int n_in,
                              void* d_out, int out_size) {
    const int* x           = (const int*)d_in[0];
    const float* in_scales = (const float*)d_in[1];
    // d_in[2] = input_sum (unused)
    const int* qweight     = (const int*)d_in[3];
    const int* s2_scales   = (const int*)d_in[4];
    const int* s2_zeros    = (const int*)d_in[5];
    const float* s1_scales = (const float*)d_in[6];
    const float* bias      = (const float*)d_in[7];
    float* out             = (float*)d_out;
    (void)in_sizes; (void)n_in; (void)out_size;

    int dev = 0, nsm = 148;
    cudaGetDevice(&dev);
    cudaDeviceGetAttribute(&nsm, cudaDevAttrMultiProcessorCount, dev);
    int grid = 4 * nsm;                 // one full occ-4 residency, no ragged waves
    if (grid > kTiles) grid = kTiles;

    pack_x_kernel<<<(kM * kK / 4) / kThreads, kThreads>>>(x, grid);
    w4a8_gemm<<<grid, kThreads>>>(qweight, s2_scales, s2_zeros,
                                  in_scales, s1_scales, bias, out);
}

// round 13
// speedup vs baseline: 4.7904x; 1.2916x over previous
#include <cuda_runtime.h>
#include <cstdint>
#include <cstddef>

namespace {
constexpr int kM = 64;
constexpr int kK = 4096;
constexpr int kN = 14336;
constexpr int kBN = 16;               // tile width -> grid 896
constexpr int kBK = 128;              // one quant group per chunk
constexpr int kChunks = kK / kBK;     // 32
constexpr int kPad = 144;             // smem row stride (conflict-free ldmatrix)
constexpr int kAStage = 64 * kPad;    // 9216 B
constexpr int kBStage = kBN * kPad;   // 2304 B
constexpr int kThreads = 256;
}

// device-global scratch (no allocations allowed)
__device__ __align__(16) int8_t g_x8[kM * kK];  // packed int8 activations

__global__ void pack_x_kernel(const int* __restrict__ x) {
    int idx = blockIdx.x * blockDim.x + threadIdx.x;  // int4 index over M*K/4
    int4 v = __ldg(((const int4*)x) + idx);
    uint32_t w = (uint32_t)(v.x & 0xff) | ((uint32_t)(v.y & 0xff) << 8)
               | ((uint32_t)(v.z & 0xff) << 16) | ((uint32_t)(v.w & 0xff) << 24);
    ((uint32_t*)g_x8)[idx] = w;
}

// ---------------- PTX helpers ----------------
__device__ __forceinline__ uint32_t smem_u32(const void* p) {
    return (uint32_t)__cvta_generic_to_shared(p);
}
__device__ __forceinline__ void cp_async16(uint32_t dst, const void* src) {
    asm volatile("cp.async.ca.shared.global [%0], [%1], 16;\n" :: "r"(dst), "l"(src));
}
__device__ __forceinline__ void cp_commit() { asm volatile("cp.async.commit_group;\n"); }
template <int N>
__device__ __forceinline__ void cp_wait() {
    asm volatile("cp.async.wait_group %0;\n" :: "n"(N) : "memory");
}
__device__ __forceinline__ uint32_t prmt(uint32_t a, uint32_t b, uint32_t sel) {
    uint32_t d;
    asm("prmt.b32 %0, %1, %2, %3;" : "=r"(d) : "r"(a), "r"(b), "r"(sel));
    return d;
}
__device__ __forceinline__ void ldmatrix_x4(uint32_t r[4], uint32_t addr) {
    asm volatile("ldmatrix.sync.aligned.m8n8.x4.shared.b16 {%0,%1,%2,%3}, [%4];"
                 : "=r"(r[0]), "=r"(r[1]), "=r"(r[2]), "=r"(r[3]) : "r"(addr));
}
__device__ __forceinline__ void mma_s8(int c[4], uint32_t a0, uint32_t a1, uint32_t a2,
                                       uint32_t a3, uint32_t b0, uint32_t b1) {
    asm volatile(
        "mma.sync.aligned.m16n8k32.row.col.s32.s8.s8.s32 "
        "{%0,%1,%2,%3}, {%4,%5,%6,%7}, {%8,%9}, {%0,%1,%2,%3};\n"
        : "+r"(c[0]), "+r"(c[1]), "+r"(c[2]), "+r"(c[3])
        : "r"(a0), "r"(a1), "r"(a2), "r"(a3), "r"(b0), "r"(b1));
}

// ---- cooperative GEMM: R6 + 3-stage A ring (wait<1>) + STS-before-mma, occ 4 ----
__global__ void __launch_bounds__(kThreads, 4)
w4a8_gemm(const int* __restrict__ qweight,
          const int* __restrict__ s2_scales,
          const int* __restrict__ s2_zeros,
          const float* __restrict__ input_scales,
          const float* __restrict__ s1_scales,
          const float* __restrict__ bias,
          float* __restrict__ out) {
    __shared__ __align__(16) int8_t As[3][kAStage];   // 3-stage A ring
    __shared__ __align__(16) int8_t Bs[2][kBStage];   // 2-stage B

    const int tid = threadIdx.x;
    const int warp = tid >> 5;
    const int lane = tid & 31;
    const int n0 = blockIdx.x * kBN;

    // ---- producer mapping: 16 rows x 16 segments (8 values each) ----
    const int nl = tid >> 4;           // 0..15 weight row in tile
    const int seg = tid & 15;          // 8-value segment within the 128-wide chunk
    const int n_glob = n0 + nl;
    const int4* qrow = (const int4*)qweight + (size_t)n_glob * (kK / 4);

    // depth-2 register prefetch: chunk j lives in slot j&1
    int4 qv0[2], qv1[2];
    int s2r[2], zr[2];

    auto ldg_chunk = [&](int c) {
        const int b = c & 1;
        qv0[b] = __ldcs(qrow + c * 32 + seg * 2);
        qv1[b] = __ldcs(qrow + c * 32 + seg * 2 + 1);
        s2r[b] = __ldg(s2_scales + c * kN + n_glob);
        zr[b]  = __ldg(s2_zeros + c * kN + n_glob);
    };
    auto cp_a = [&](int c, int s) {
#pragma unroll
        for (int j = 0; j < 2; ++j) {
            int id = tid + kThreads * j;           // 0..511
            int row = id >> 3, sg = id & 7;
            cp_async16(smem_u32(&As[s][row * kPad + sg * 16]),
                       g_x8 + (size_t)row * kK + c * kBK + sg * 16);
        }
        cp_commit();
    };
    auto dequant_sts = [&](int c, int s) {
        const int b = c & 1;
        const int sc = s2r[b], zc = zr[b];
        int b0 = qv0[b].x * sc + zc, b1 = qv0[b].y * sc + zc;
        int b2 = qv0[b].z * sc + zc, b3 = qv0[b].w * sc + zc;
        uint32_t p01 = prmt((uint32_t)b0, (uint32_t)b1, 0x0040);
        uint32_t p23 = prmt((uint32_t)b2, (uint32_t)b3, 0x0040);
        uint32_t pk0 = prmt(p01, p23, 0x5410);
        int c0 = qv1[b].x * sc + zc, c1 = qv1[b].y * sc + zc;
        int c2 = qv1[b].z * sc + zc, c3 = qv1[b].w * sc + zc;
        uint32_t q01 = prmt((uint32_t)c0, (uint32_t)c1, 0x0040);
        uint32_t q23 = prmt((uint32_t)c2, (uint32_t)c3, 0x0040);
        uint32_t pk1 = prmt(q01, q23, 0x5410);
        *(uint2*)(&Bs[s][nl * kPad + seg * 8]) = make_uint2(pk0, pk1);
    };

    // ---- consumer mapping (validated): warp -> (m-tile, n-tile) ----
    const int mt = warp & 3;       // 16-row m-tile
    const int nt = warp >> 2;      // 8-col n-tile
    const uint32_t a_off = (uint32_t)((mt * 16 + (lane & 7) + ((lane >> 3) & 1) * 8) * kPad
                                      + ((lane >> 4) & 1) * 16);
    const uint32_t b_off = (uint32_t)((nt * 8 + (lane & 7)) * kPad + (lane >> 3) * 16);
    int acc[2][4] = {};   // two independent chains (k-halves of each chunk)

    // ---- prologue: q chunks 0,1 in regs; A stages 0,1 in flight; B chunk 0 built
    ldg_chunk(0);
    ldg_chunk(1);
    cp_a(0, 0);
    cp_a(1, 1);
    dequant_sts(0, 0);
    cp_wait<1>();                 // A stage 0 complete (stage 1 may still fly)
    __syncthreads();

    for (int c = 0; c < kChunks; ++c) {
        const int sA = c % 3;
        const int sB = c & 1;
        if (c + 2 < kChunks) {
            ldg_chunk(c + 2);               // q for chunk c+2 (long distance)
            cp_a(c + 2, (c + 2) % 3);       // A stage c+2 (stage free since c-1)
        }
        // build B for chunk c+1 BEFORE the mma section (STS drains under mma)
        if (c + 1 < kChunks) dequant_sts(c + 1, sB ^ 1);

        const uint32_t abase = smem_u32(&As[sA][0]) + a_off;
        const uint32_t bbase = smem_u32(&Bs[sB][0]) + b_off;
#pragma unroll
        for (int kp = 0; kp < 2; ++kp) {
            uint32_t bf[4];
            ldmatrix_x4(bf, bbase + kp * 64);
#pragma unroll
            for (int k2 = 0; k2 < 2; ++k2) {
                uint32_t a[4];
                ldmatrix_x4(a, abase + (kp * 2 + k2) * 32);
                mma_s8(acc[kp], a[0], a[1], a[2], a[3], bf[k2 * 2], bf[k2 * 2 + 1]);
            }
        }

        if (c + 2 < kChunks) cp_wait<1>();  // A stage c+1 done; c+2 may fly
        else                 cp_wait<0>();  // tail drain
        __syncthreads();
    }

    // ---- fused epilogue (merge the two chains) ----
    const int r = mt * 16 + (lane >> 2);
    const int n = n0 + nt * 8 + (lane & 3) * 2;
    const float is0 = input_scales[r];
    const float is1 = input_scales[r + 8];
    const float s1a = s1_scales[n], s1b = s1_scales[n + 1];
    const float ba = bias[n], bb = bias[n + 1];
    const int a0 = acc[0][0] + acc[1][0], a1 = acc[0][1] + acc[1][1];
    const int a2 = acc[0][2] + acc[1][2], a3 = acc[0][3] + acc[1][3];
    *(float2*)(out + (size_t)r * kN + n) =
        make_float2((float)a0 * is0 * s1a + ba, (float)a1 * is0 * s1b + bb);
    *(float2*)(out + (size_t)(r + 8) * kN + n) =
        make_float2((float)a2 * is1 * s1a + ba, (float)a3 * is1 * s1b + bb);
}

extern "C" void kernel_launch(void* const* d_in, const int* in_sizes, int n_in,
                              void* d_out, int out_size) {
    const int* x           = (const int*)d_in[0];
    const float* in_scales = (const float*)d_in[1];
    // d_in[2] = input_sum (unused)
    const int* qweight     = (const int*)d_in[3];
    const int* s2_scales   = (const int*)d_in[4];
    const int* s2_zeros    = (const int*)d_in[5];
    const float* s1_scales = (const float*)d_in[6];
    const float* bias      = (const float*)d_in[7];
    float* out             = (float*)d_out;
    (void)in_sizes; (void)n_in; (void)out_size;

    pack_x_kernel<<<(kM * kK / 4) / kThreads, kThreads>>>(x);
    w4a8_gemm<<<kN / kBN, kThreads>>>(qweight, s2_scales, s2_zeros,
                                      in_scales, s1_scales, bias, out);
}

// round 14
// speedup vs baseline: 4.8794x; 1.0186x over previous
#include <cuda_runtime.h>
#include <cstdint>
#include <cstddef>

namespace {
constexpr int kM = 64;
constexpr int kK = 4096;
constexpr int kN = 14336;
constexpr int kBN = 16;               // tile width -> grid 896
constexpr int kBK = 128;              // one quant group per chunk
constexpr int kChunks = kK / kBK;     // 32
constexpr int kPad = 144;             // smem row stride (conflict-free ldmatrix)
constexpr int kAStage = 64 * kPad;    // 9216 B
constexpr int kBStage = kBN * kPad;   // 2304 B
constexpr int kThreads = 256;
}

// device-global scratch (no allocations allowed)
__device__ __align__(16) int8_t g_x8[kM * kK];  // packed int8 activations

__global__ void pack_x_kernel(const int* __restrict__ x) {
    int idx = blockIdx.x * blockDim.x + threadIdx.x;  // int4 index over M*K/4
    int4 v = __ldg(((const int4*)x) + idx);
    uint32_t w = (uint32_t)(v.x & 0xff) | ((uint32_t)(v.y & 0xff) << 8)
               | ((uint32_t)(v.z & 0xff) << 16) | ((uint32_t)(v.w & 0xff) << 24);
    ((uint32_t*)g_x8)[idx] = w;
}

// ---------------- PTX helpers ----------------
__device__ __forceinline__ uint32_t smem_u32(const void* p) {
    return (uint32_t)__cvta_generic_to_shared(p);
}
__device__ __forceinline__ void cp_async16(uint32_t dst, const void* src) {
    asm volatile("cp.async.ca.shared.global [%0], [%1], 16;\n" :: "r"(dst), "l"(src));
}
__device__ __forceinline__ void cp_commit() { asm volatile("cp.async.commit_group;\n"); }
template <int N>
__device__ __forceinline__ void cp_wait() {
    asm volatile("cp.async.wait_group %0;\n" :: "n"(N) : "memory");
}
__device__ __forceinline__ uint32_t prmt(uint32_t a, uint32_t b, uint32_t sel) {
    uint32_t d;
    asm("prmt.b32 %0, %1, %2, %3;" : "=r"(d) : "r"(a), "r"(b), "r"(sel));
    return d;
}
__device__ __forceinline__ void ldmatrix_x4(uint32_t r[4], uint32_t addr) {
    asm volatile("ldmatrix.sync.aligned.m8n8.x4.shared.b16 {%0,%1,%2,%3}, [%4];"
                 : "=r"(r[0]), "=r"(r[1]), "=r"(r[2]), "=r"(r[3]) : "r"(addr));
}
__device__ __forceinline__ void mma_s8(int c[4], uint32_t a0, uint32_t a1, uint32_t a2,
                                       uint32_t a3, uint32_t b0, uint32_t b1) {
    asm volatile(
        "mma.sync.aligned.m16n8k32.row.col.s32.s8.s8.s32 "
        "{%0,%1,%2,%3}, {%4,%5,%6,%7}, {%8,%9}, {%0,%1,%2,%3};\n"
        : "+r"(c[0]), "+r"(c[1]), "+r"(c[2]), "+r"(c[3])
        : "r"(a0), "r"(a1), "r"(a2), "r"(a3), "r"(b0), "r"(b1));
}

// ---- cooperative GEMM: R6 verbatim, single delta = 3-stage A ring + wait<1> ----
__global__ void __launch_bounds__(kThreads, 4)
w4a8_gemm(const int* __restrict__ qweight,
          const int* __restrict__ s2_scales,
          const int* __restrict__ s2_zeros,
          const float* __restrict__ input_scales,
          const float* __restrict__ s1_scales,
          const float* __restrict__ bias,
          float* __restrict__ out) {
    __shared__ __align__(16) int8_t As[3][kAStage];   // 3-stage A ring
    __shared__ __align__(16) int8_t Bs[2][kBStage];   // 2-stage B (as R6)

    const int tid = threadIdx.x;
    const int warp = tid >> 5;
    const int lane = tid & 31;
    const int n0 = blockIdx.x * kBN;

    // ---- producer mapping: 16 rows x 16 segments (8 values each) ----
    const int nl = tid >> 4;           // 0..15 weight row in tile
    const int seg = tid & 15;          // 8-value segment within the 128-wide chunk
    const int n_glob = n0 + nl;
    const int4* qrow = (const int4*)qweight + (size_t)n_glob * (kK / 4);

    // depth-2 register prefetch: chunk j lives in slot j&1
    int4 qv0[2], qv1[2];
    int s2r[2], zr[2];

    auto ldg_chunk = [&](int c) {
        const int b = c & 1;
        qv0[b] = __ldcs(qrow + c * 32 + seg * 2);
        qv1[b] = __ldcs(qrow + c * 32 + seg * 2 + 1);
        s2r[b] = __ldg(s2_scales + c * kN + n_glob);
        zr[b]  = __ldg(s2_zeros + c * kN + n_glob);
    };
    auto cp_a = [&](int c, int s) {
#pragma unroll
        for (int j = 0; j < 2; ++j) {
            int id = tid + kThreads * j;           // 0..511
            int row = id >> 3, sg = id & 7;
            cp_async16(smem_u32(&As[s][row * kPad + sg * 16]),
                       g_x8 + (size_t)row * kK + c * kBK + sg * 16);
        }
        cp_commit();
    };
    auto dequant_sts = [&](int c, int s) {
        const int b = c & 1;
        const int sc = s2r[b], zc = zr[b];
        int b0 = qv0[b].x * sc + zc, b1 = qv0[b].y * sc + zc;
        int b2 = qv0[b].z * sc + zc, b3 = qv0[b].w * sc + zc;
        uint32_t p01 = prmt((uint32_t)b0, (uint32_t)b1, 0x0040);
        uint32_t p23 = prmt((uint32_t)b2, (uint32_t)b3, 0x0040);
        uint32_t pk0 = prmt(p01, p23, 0x5410);
        int c0 = qv1[b].x * sc + zc, c1 = qv1[b].y * sc + zc;
        int c2 = qv1[b].z * sc + zc, c3 = qv1[b].w * sc + zc;
        uint32_t q01 = prmt((uint32_t)c0, (uint32_t)c1, 0x0040);
        uint32_t q23 = prmt((uint32_t)c2, (uint32_t)c3, 0x0040);
        uint32_t pk1 = prmt(q01, q23, 0x5410);
        *(uint2*)(&Bs[s][nl * kPad + seg * 8]) = make_uint2(pk0, pk1);
    };

    // ---- consumer mapping (validated): warp -> (m-tile, n-tile) ----
    const int mt = warp & 3;       // 16-row m-tile
    const int nt = warp >> 2;      // 8-col n-tile
    const uint32_t a_off = (uint32_t)((mt * 16 + (lane & 7) + ((lane >> 3) & 1) * 8) * kPad
                                      + ((lane >> 4) & 1) * 16);
    const uint32_t b_off = (uint32_t)((nt * 8 + (lane & 7)) * kPad + (lane >> 3) * 16);
    int acc[2][4] = {};   // two independent chains (k-halves of each chunk)

    // ---- prologue: q chunks 0,1 in regs; A stages 0,1 in flight; B chunk 0 built
    ldg_chunk(0);
    ldg_chunk(1);
    cp_a(0, 0);
    cp_a(1, 1);
    dequant_sts(0, 0);
    cp_wait<1>();                 // A stage 0 complete (stage 1 may still fly)
    __syncthreads();

    for (int c = 0; c < kChunks; ++c) {
        const int sA = c % 3;
        const int sB = c & 1;
        if (c + 2 < kChunks) {
            ldg_chunk(c + 2);               // q for chunk c+2 (long distance)
            cp_a(c + 2, (c + 2) % 3);       // A stage c+2 (stage free since c-1)
        }

        const uint32_t abase = smem_u32(&As[sA][0]) + a_off;
        const uint32_t bbase = smem_u32(&Bs[sB][0]) + b_off;
#pragma unroll
        for (int kp = 0; kp < 2; ++kp) {
            uint32_t bf[4];
            ldmatrix_x4(bf, bbase + kp * 64);
#pragma unroll
            for (int k2 = 0; k2 < 2; ++k2) {
                uint32_t a[4];
                ldmatrix_x4(a, abase + (kp * 2 + k2) * 32);
                mma_s8(acc[kp], a[0], a[1], a[2], a[3], bf[k2 * 2], bf[k2 * 2 + 1]);
            }
        }

        // R6 order: dequant AFTER mma (mma covers the q-load latency)
        if (c + 1 < kChunks) dequant_sts(c + 1, sB ^ 1);
        if (c + 2 < kChunks) cp_wait<1>();  // waited group was issued LAST iteration
        else                 cp_wait<0>();  // tail drain
        __syncthreads();
    }

    // ---- fused epilogue (merge the two chains) ----
    const int r = mt * 16 + (lane >> 2);
    const int n = n0 + nt * 8 + (lane & 3) * 2;
    const float is0 = input_scales[r];
    const float is1 = input_scales[r + 8];
    const float s1a = s1_scales[n], s1b = s1_scales[n + 1];
    const float ba = bias[n], bb = bias[n + 1];
    const int a0 = acc[0][0] + acc[1][0], a1 = acc[0][1] + acc[1][1];
    const int a2 = acc[0][2] + acc[1][2], a3 = acc[0][3] + acc[1][3];
    *(float2*)(out + (size_t)r * kN + n) =
        make_float2((float)a0 * is0 * s1a + ba, (float)a1 * is0 * s1b + bb);
    *(float2*)(out + (size_t)(r + 8) * kN + n) =
        make_float2((float)a2 * is1 * s1a + ba, (float)a3 * is1 * s1b + bb);
}

extern "C" void kernel_launch(void* const* d_in, const int* in_sizes, int n_in,
                              void* d_out, int out_size) {
    const int* x           = (const int*)d_in[0];
    const float* in_scales = (const float*)d_in[1];
    // d_in[2] = input_sum (unused)
    const int* qweight     = (const int*)d_in[3];
    const int* s2_scales   = (const int*)d_in[4];
    const int* s2_zeros    = (const int*)d_in[5];
    const float* s1_scales = (const float*)d_in[6];
    const float* bias      = (const float*)d_in[7];
    float* out             = (float*)d_out;
    (void)in_sizes; (void)n_in; (void)out_size;

    pack_x_kernel<<<(kM * kK / 4) / kThreads, kThreads>>>(x);
    w4a8_gemm<<<kN / kBN, kThreads>>>(qweight, s2_scales, s2_zeros,
                                      in_scales, s1_scales, bias, out);
}

// round 15
// speedup vs baseline: 7.1323x; 1.4617x over previous
#include <cuda_runtime.h>
#include <cstdint>
#include <cstddef>

namespace {
constexpr int kM = 64;
constexpr int kK = 4096;
constexpr int kN = 14336;
constexpr int kBN = 16;               // tile width
constexpr int kBK = 128;              // one quant group per chunk
constexpr int kSplit = 2;             // K-split -> finer work quantum
constexpr int kKper = kK / kSplit;    // 2048 (int32 elements of x/q per split)
constexpr int kChunks = kKper / kBK;  // 16 chunks per CTA
constexpr int kTiles = kN / kBN;      // 896 -> grid 1792
constexpr int kPad = 144;             // smem row stride (conflict-free ldmatrix)
constexpr int kAStage = 64 * kPad;    // 9216 B
constexpr int kBStage = kBN * kPad;   // 2304 B
constexpr int kThreads = 256;
}

// device-global scratch (no allocations allowed)
__device__ __align__(16) int8_t g_x8[kM * kK];       // packed int8 activations
__device__ __align__(16) int g_part[kSplit][kM * kN];  // int32 split partials

__global__ void pack_x_kernel(const int* __restrict__ x) {
    int idx = blockIdx.x * blockDim.x + threadIdx.x;  // int4 index over M*K/4
    int4 v = __ldg(((const int4*)x) + idx);
    uint32_t w = (uint32_t)(v.x & 0xff) | ((uint32_t)(v.y & 0xff) << 8)
               | ((uint32_t)(v.z & 0xff) << 16) | ((uint32_t)(v.w & 0xff) << 24);
    ((uint32_t*)g_x8)[idx] = w;
}

// ---------------- PTX helpers ----------------
__device__ __forceinline__ uint32_t smem_u32(const void* p) {
    return (uint32_t)__cvta_generic_to_shared(p);
}
__device__ __forceinline__ void cp_async16(uint32_t dst, const void* src) {
    asm volatile("cp.async.ca.shared.global [%0], [%1], 16;\n" :: "r"(dst), "l"(src));
}
__device__ __forceinline__ void cp_commit() { asm volatile("cp.async.commit_group;\n"); }
__device__ __forceinline__ void cp_wait_all() { asm volatile("cp.async.wait_group 0;\n" ::: "memory"); }
__device__ __forceinline__ uint32_t prmt(uint32_t a, uint32_t b, uint32_t sel) {
    uint32_t d;
    asm("prmt.b32 %0, %1, %2, %3;" : "=r"(d) : "r"(a), "r"(b), "r"(sel));
    return d;
}
__device__ __forceinline__ void ldmatrix_x4(uint32_t r[4], uint32_t addr) {
    asm volatile("ldmatrix.sync.aligned.m8n8.x4.shared.b16 {%0,%1,%2,%3}, [%4];"
                 : "=r"(r[0]), "=r"(r[1]), "=r"(r[2]), "=r"(r[3]) : "r"(addr));
}
__device__ __forceinline__ void mma_s8(int c[4], uint32_t a0, uint32_t a1, uint32_t a2,
                                       uint32_t a3, uint32_t b0, uint32_t b1) {
    asm volatile(
        "mma.sync.aligned.m16n8k32.row.col.s32.s8.s8.s32 "
        "{%0,%1,%2,%3}, {%4,%5,%6,%7}, {%8,%9}, {%0,%1,%2,%3};\n"
        : "+r"(c[0]), "+r"(c[1]), "+r"(c[2]), "+r"(c[3])
        : "r"(a0), "r"(a1), "r"(a2), "r"(a3), "r"(b0), "r"(b1));
}

// ---- cooperative GEMM: R6 loop verbatim, split-K=2 (uniform k0 base), occ 4 ----
__global__ void __launch_bounds__(kThreads, 4)
w4a8_gemm(const int* __restrict__ qweight,
          const int* __restrict__ s2_scales,
          const int* __restrict__ s2_zeros) {
    __shared__ __align__(16) int8_t As[2][kAStage];
    __shared__ __align__(16) int8_t Bs[2][kBStage];

    const int tid = threadIdx.x;
    const int warp = tid >> 5;
    const int lane = tid & 31;
    const int tile = blockIdx.x >> 1;
    const int split = blockIdx.x & 1;
    const int n0 = tile * kBN;
    const int grp0 = split * kChunks;          // first quant group of this split

    // ---- producer mapping: 16 rows x 16 segments (8 values each) ----
    const int nl = tid >> 4;           // 0..15 weight row in tile
    const int seg = tid & 15;          // 8-value segment within the 128-wide chunk
    const int n_glob = n0 + nl;
    // uniform split base: kKper int32 = kKper/4 int4 units
    const int4* qrow = (const int4*)qweight + (size_t)n_glob * (kK / 4)
                       + split * (kKper / 4);

    // depth-2 register prefetch: chunk j lives in slot j&1
    int4 qv0[2], qv1[2];
    int s2r[2], zr[2];

    auto ldg_chunk = [&](int c) {
        const int b = c & 1;
        qv0[b] = __ldcs(qrow + c * 32 + seg * 2);
        qv1[b] = __ldcs(qrow + c * 32 + seg * 2 + 1);
        s2r[b] = __ldg(s2_scales + (grp0 + c) * kN + n_glob);
        zr[b]  = __ldg(s2_zeros + (grp0 + c) * kN + n_glob);
    };
    auto cp_a = [&](int c, int s) {
#pragma unroll
        for (int j = 0; j < 2; ++j) {
            int id = tid + kThreads * j;           // 0..511
            int row = id >> 3, sg = id & 7;
            cp_async16(smem_u32(&As[s][row * kPad + sg * 16]),
                       g_x8 + (size_t)row * kK + split * kKper + c * kBK + sg * 16);
        }
        cp_commit();
    };
    auto dequant_sts = [&](int c, int s) {
        const int b = c & 1;
        const int sc = s2r[b], zc = zr[b];
        int b0 = qv0[b].x * sc + zc, b1 = qv0[b].y * sc + zc;
        int b2 = qv0[b].z * sc + zc, b3 = qv0[b].w * sc + zc;
        uint32_t p01 = prmt((uint32_t)b0, (uint32_t)b1, 0x0040);
        uint32_t p23 = prmt((uint32_t)b2, (uint32_t)b3, 0x0040);
        uint32_t pk0 = prmt(p01, p23, 0x5410);
        int c0 = qv1[b].x * sc + zc, c1 = qv1[b].y * sc + zc;
        int c2 = qv1[b].z * sc + zc, c3 = qv1[b].w * sc + zc;
        uint32_t q01 = prmt((uint32_t)c0, (uint32_t)c1, 0x0040);
        uint32_t q23 = prmt((uint32_t)c2, (uint32_t)c3, 0x0040);
        uint32_t pk1 = prmt(q01, q23, 0x5410);
        *(uint2*)(&Bs[s][nl * kPad + seg * 8]) = make_uint2(pk0, pk1);
    };

    // ---- consumer mapping (validated): warp -> (m-tile, n-tile) ----
    const int mt = warp & 3;       // 16-row m-tile
    const int nt = warp >> 2;      // 8-col n-tile
    const uint32_t a_off = (uint32_t)((mt * 16 + (lane & 7) + ((lane >> 3) & 1) * 8) * kPad
                                      + ((lane >> 4) & 1) * 16);
    const uint32_t b_off = (uint32_t)((nt * 8 + (lane & 7)) * kPad + (lane >> 3) * 16);
    int acc[2][4] = {};   // two independent chains (k-halves of each chunk)

    // ---- prologue: chunks 0 and 1 in regs; stage 0 built (exactly as R6) ----
    ldg_chunk(0);
    ldg_chunk(1);
    cp_a(0, 0);
    dequant_sts(0, 0);
    cp_wait_all();
    __syncthreads();

    for (int c = 0; c < kChunks; ++c) {
        const int s = c & 1;
        if (c + 2 < kChunks) ldg_chunk(c + 2);
        if (c + 1 < kChunks) cp_a(c + 1, s ^ 1);

        const uint32_t abase = smem_u32(&As[s][0]) + a_off;
        const uint32_t bbase = smem_u32(&Bs[s][0]) + b_off;
#pragma unroll
        for (int kp = 0; kp < 2; ++kp) {
            uint32_t bf[4];
            ldmatrix_x4(bf, bbase + kp * 64);
#pragma unroll
            for (int k2 = 0; k2 < 2; ++k2) {
                uint32_t a[4];
                ldmatrix_x4(a, abase + (kp * 2 + k2) * 32);
                mma_s8(acc[kp], a[0], a[1], a[2], a[3], bf[k2 * 2], bf[k2 * 2 + 1]);
            }
        }

        if (c + 1 < kChunks) dequant_sts(c + 1, s ^ 1);
        cp_wait_all();
        __syncthreads();
    }

    // ---- store int32 partials for this split (exact) ----
    const int r = mt * 16 + (lane >> 2);
    const int n = n0 + nt * 8 + (lane & 3) * 2;
    const int a0 = acc[0][0] + acc[1][0], a1 = acc[0][1] + acc[1][1];
    const int a2 = acc[0][2] + acc[1][2], a3 = acc[0][3] + acc[1][3];
    int* pbase = &g_part[split][0];
    *(int2*)(pbase + (size_t)r * kN + n) = make_int2(a0, a1);
    *(int2*)(pbase + (size_t)(r + 8) * kN + n) = make_int2(a2, a3);
}

// ---------------- epilogue: sum splits, scale, bias (validated R4) ----------------
__global__ void epilogue_kernel(const float* __restrict__ input_scales,
                                const float* __restrict__ s1_scales,
                                const float* __restrict__ bias,
                                float* __restrict__ out) {
    int idx = blockIdx.x * blockDim.x + threadIdx.x;  // quad index over M*N/4
    int m = idx / (kN / 4);
    int n = (idx - m * (kN / 4)) * 4;
    int4 p0 = *(const int4*)&g_part[0][(size_t)m * kN + n];
    int4 p1 = *(const int4*)&g_part[1][(size_t)m * kN + n];
    float is = input_scales[m];
    float4 s = *(const float4*)(s1_scales + n);
    float4 b = *(const float4*)(bias + n);
    float4 o;
    o.x = (float)(p0.x + p1.x) * is * s.x + b.x;
    o.y = (float)(p0.y + p1.y) * is * s.y + b.y;
    o.z = (float)(p0.z + p1.z) * is * s.z + b.z;
    o.w = (float)(p0.w + p1.w) * is * s.w + b.w;
    *(float4*)(out + (size_t)m * kN + n) = o;
}

extern "C" void kernel_launch(void* const* d_in, const int* in_sizes, int n_in,
                              void* d_out, int out_size) {
    const int* x           = (const int*)d_in[0];
    const float* in_scales = (const float*)d_in[1];
    // d_in[2] = input_sum (unused)
    const int* qweight     = (const int*)d_in[3];
    const int* s2_scales   = (const int*)d_in[4];
    const int* s2_zeros    = (const int*)d_in[5];
    const float* s1_scales = (const float*)d_in[6];
    const float* bias      = (const float*)d_in[7];
    float* out             = (float*)d_out;
    (void)in_sizes; (void)n_in; (void)out_size;

    pack_x_kernel<<<(kM * kK / 4) / kThreads, kThreads>>>(x);
    w4a8_gemm<<<kTiles * kSplit, kThreads>>>(qweight, s2_scales, s2_zeros);
    epilogue_kernel<<<(kM * kN / 4) / 512, 512>>>(in_scales, s1_scales, bias, out);
}